// round 1
// baseline (speedup 1.0000x reference)
#include <cuda_runtime.h>
#include <math.h>

#define BB 2
#define TT 4096
#define DD 128
#define KK 256
#define BT (BB * TT)

// ---------------- scratch (static __device__, no allocation) ----------------
__device__ float g_kh[BT * DD];   // k_hat
__device__ float g_mf[BT * DD];   // memory_force
__device__ float g_qh[BT * DD];   // q_hat (per stage)
__device__ float g_a0[BT * DD];   // attention partial 0
__device__ float g_a1[BT * DD];   // attention partial 1
__device__ float g_zc[BT * DD];   // current z (retracted)
__device__ float g_va[BT * DD];   // RK4 accumulated v

// ---------------- depthwise causal conv ----------------
// mf[b,t,d] = bias[d] + sum_k z[b, t-K+1+k, d] * w[k, d]   (XLA cross-correlation)
__global__ __launch_bounds__(512) void conv_kernel(const float* __restrict__ z,
                                                   const float* __restrict__ w,
                                                   const float* __restrict__ bias,
                                                   float* __restrict__ mf) {
    int d = threadIdx.x;
    int t = blockIdx.x * 4 + threadIdx.y;
    int b = blockIdx.y;
    float acc = bias[d];
    int kstart = (KK - 1) - t;
    if (kstart < 0) kstart = 0;
    const float* zp = z + ((long long)b * TT + t - (KK - 1)) * DD + d;
    const float* wp = w + d;
#pragma unroll 4
    for (int k = kstart; k < KK; k++)
        acc = fmaf(zp[(long long)k * DD], wp[(long long)k * DD], acc);
    mf[((long long)b * TT + t) * DD + d] = acc;
}

// ---------------- block reduce of 4 values (128 threads) ----------------
__device__ __forceinline__ void block_reduce4(float v[4], float* red) {
#pragma unroll
    for (int k = 0; k < 4; k++) {
        float x = v[k];
#pragma unroll
        for (int o = 16; o; o >>= 1) x += __shfl_xor_sync(0xffffffffu, x, o);
        if ((threadIdx.x & 31) == 0) red[((threadIdx.x >> 5) << 2) + k] = x;
    }
    __syncthreads();
#pragma unroll
    for (int k = 0; k < 4; k++) v[k] = red[k] + red[4 + k] + red[8 + k] + red[12 + k];
    __syncthreads();
}

// ---------------- Y = sphere_norm(X @ W + bias), rows of length 128 ----------------
__global__ __launch_bounds__(128) void gemm_norm_kernel(const float* __restrict__ X,
                                                        const float* __restrict__ W,
                                                        const float* __restrict__ bias,
                                                        float* __restrict__ Y) {
    extern __shared__ float sm[];
    float* Ws  = sm;           // 128*128
    float* xs  = sm + 16384;   // 4*128
    float* red = sm + 16896;   // 16
    int d = threadIdx.x;
    for (int idx = d; idx < 16384; idx += 128) Ws[idx] = W[idx];
    float bv = bias[d];
    __syncthreads();
    long long row0 = (long long)blockIdx.x * 16;
    for (int g = 0; g < 16; g += 4) {
#pragma unroll
        for (int k = 0; k < 4; k++) xs[k * 128 + d] = X[(row0 + g + k) * DD + d];
        __syncthreads();
        float a0 = bv, a1 = bv, a2 = bv, a3 = bv;
#pragma unroll 4
        for (int j = 0; j < 128; j++) {
            float wv = Ws[j * 128 + d];
            a0 = fmaf(xs[j], wv, a0);
            a1 = fmaf(xs[128 + j], wv, a1);
            a2 = fmaf(xs[256 + j], wv, a2);
            a3 = fmaf(xs[384 + j], wv, a3);
        }
        float acc[4] = {a0, a1, a2, a3};
        float v[4] = {a0 * a0, a1 * a1, a2 * a2, a3 * a3};
        block_reduce4(v, red);
#pragma unroll
        for (int k = 0; k < 4; k++) {
            float norm = fmaxf(sqrtf(v[k]), 1e-8f);
            Y[(row0 + g + k) * DD + d] = __fdividef(acc[k], norm);
        }
        __syncthreads();
    }
}

// ---------------- fused epilogue ----------------
// a = A0+A1 ; y = a @ Wo + bo ; tot = mf + y ; proj = tot - (tot.zc) zc
// vacc (+)= sw*proj ; if has_next: zout = sphere_norm(zbase + rc*proj)
__global__ __launch_bounds__(128) void epilogue_kernel(
    const float* __restrict__ A0, const float* __restrict__ A1,
    const float* __restrict__ W, const float* __restrict__ bo,
    const float* __restrict__ mf, const float* __restrict__ zin,
    const float* __restrict__ zbase, float* __restrict__ vacc,
    float* __restrict__ zout, float sw, float rc, int first, int has_next) {
    extern __shared__ float sm[];
    float* Ws  = sm;
    float* xs  = sm + 16384;
    float* red = sm + 16896;
    int d = threadIdx.x;
    for (int idx = d; idx < 16384; idx += 128) Ws[idx] = W[idx];
    float bv = bo[d];
    __syncthreads();
    long long row0 = (long long)blockIdx.x * 16;
    for (int g = 0; g < 16; g += 4) {
#pragma unroll
        for (int k = 0; k < 4; k++) {
            long long off = (row0 + g + k) * DD + d;
            xs[k * 128 + d] = A0[off] + A1[off];
        }
        __syncthreads();
        float a0 = bv, a1 = bv, a2 = bv, a3 = bv;
#pragma unroll 4
        for (int j = 0; j < 128; j++) {
            float wv = Ws[j * 128 + d];
            a0 = fmaf(xs[j], wv, a0);
            a1 = fmaf(xs[128 + j], wv, a1);
            a2 = fmaf(xs[256 + j], wv, a2);
            a3 = fmaf(xs[384 + j], wv, a3);
        }
        float acc[4] = {a0, a1, a2, a3};
        float tot[4], zcd[4], v[4];
#pragma unroll
        for (int k = 0; k < 4; k++) {
            long long off = (row0 + g + k) * DD + d;
            tot[k] = acc[k] + mf[off];
            zcd[k] = zin[off];
            v[k]   = tot[k] * zcd[k];
        }
        block_reduce4(v, red);
        float proj[4];
#pragma unroll
        for (int k = 0; k < 4; k++) {
            proj[k] = tot[k] - v[k] * zcd[k];
            long long off = (row0 + g + k) * DD + d;
            float vp = first ? 0.f : vacc[off];
            vacc[off] = vp + sw * proj[k];
        }
        if (has_next) {
            float zn[4], u[4];
#pragma unroll
            for (int k = 0; k < 4; k++) {
                long long off = (row0 + g + k) * DD + d;
                zn[k] = zbase[off] + rc * proj[k];
                u[k]  = zn[k] * zn[k];
            }
            block_reduce4(u, red);
#pragma unroll
            for (int k = 0; k < 4; k++) {
                long long off = (row0 + g + k) * DD + d;
                zout[off] = __fdividef(zn[k], fmaxf(sqrtf(u[k]), 1e-8f));
            }
        }
        __syncthreads();
    }
}

// ---------------- causal sin-attention ----------------
// O[t,:] = sum_{s<=t} sin(q[t].k[s]) * k[s]
// BM=BN=64, 256 threads. Pair-scheduled (p, 63-p) + half-split over s for balance.
#define KR_PITCH 132

__global__ __launch_bounds__(256) void attn_kernel(const float* __restrict__ Q,
                                                   const float* __restrict__ Kh,
                                                   float* __restrict__ O0,
                                                   float* __restrict__ O1) {
    extern __shared__ float sm[];
    float* Qt = sm;             // [d][i]  128*64
    float* Kt = sm + 8192;      // [d][j]  128*64
    float* Kr = sm + 16384;     // [j][d]  64*132
    float* Ss = sm + 24832;     // [j][i]  64*64
    const int tid = threadIdx.x;
    const int b = blockIdx.z, half = blockIdx.y, p = blockIdx.x;
    float* Out = half ? O1 : O0;
    const int tj = tid & 15, ti = tid >> 4;
    const float* Qb = Q + (long long)b * TT * DD;
    const float* Kb = Kh + (long long)b * TT * DD;
    for (int rep = 0; rep < 2; rep++) {
        int tb = rep ? (TT / 64 - 1 - p) : p;
        __syncthreads();
        // load Q tile transposed (conflict-free stores)
        for (int idx = tid; idx < 2048; idx += 256) {
            int i = idx & 63, d0 = (idx >> 6) << 2;
            float4 v = *(const float4*)(Qb + ((long long)tb * 64 + i) * DD + d0);
            Qt[(d0 + 0) * 64 + i] = v.x;
            Qt[(d0 + 1) * 64 + i] = v.y;
            Qt[(d0 + 2) * 64 + i] = v.z;
            Qt[(d0 + 3) * 64 + i] = v.w;
        }
        float O[4][8];
#pragma unroll
        for (int r = 0; r < 4; r++)
#pragma unroll
            for (int c = 0; c < 8; c++) O[r][c] = 0.f;
        int nsb = tb + 1;
        int n0  = (nsb + 1) >> 1;
        int sb0 = half ? n0 : 0;
        int sb1 = half ? nsb : n0;
        for (int sb = sb0; sb < sb1; sb++) {
            __syncthreads();
            for (int idx = tid; idx < 2048; idx += 256) {
                int j = idx & 63, d0 = (idx >> 6) << 2;
                float4 v = *(const float4*)(Kb + ((long long)sb * 64 + j) * DD + d0);
                Kt[(d0 + 0) * 64 + j] = v.x;
                Kt[(d0 + 1) * 64 + j] = v.y;
                Kt[(d0 + 2) * 64 + j] = v.z;
                Kt[(d0 + 3) * 64 + j] = v.w;
                *(float4*)(Kr + j * KR_PITCH + d0) = v;
            }
            __syncthreads();
            float S[4][4];
#pragma unroll
            for (int r = 0; r < 4; r++)
#pragma unroll
                for (int c = 0; c < 4; c++) S[r][c] = 0.f;
#pragma unroll 4
            for (int dd = 0; dd < DD; dd++) {
                float4 q4 = *(const float4*)(Qt + dd * 64 + 4 * ti);
                float4 k4 = *(const float4*)(Kt + dd * 64 + 4 * tj);
                float qa[4] = {q4.x, q4.y, q4.z, q4.w};
                float kb[4] = {k4.x, k4.y, k4.z, k4.w};
#pragma unroll
                for (int r = 0; r < 4; r++)
#pragma unroll
                    for (int c = 0; c < 4; c++) S[r][c] = fmaf(qa[r], kb[c], S[r][c]);
            }
            const bool diag = (sb == tb);
            // sin via degree-9 odd Taylor, |x|<=1 (unit vectors), err <= 2.5e-8
#pragma unroll
            for (int r = 0; r < 4; r++)
#pragma unroll
                for (int c = 0; c < 4; c++) {
                    float x  = S[r][c];
                    float x2 = x * x;
                    float pp = fmaf(x2, 2.7557319e-06f, -1.9841270e-04f);
                    pp = fmaf(x2, pp, 8.3333333e-03f);
                    pp = fmaf(x2, pp, -1.6666667e-01f);
                    float sv = fmaf(x * x2, pp, x);
                    if (diag && (4 * tj + c) > (4 * ti + r)) sv = 0.f;
                    S[r][c] = sv;
                }
#pragma unroll
            for (int c = 0; c < 4; c++) {
                float4 v = make_float4(S[0][c], S[1][c], S[2][c], S[3][c]);
                *(float4*)(Ss + (4 * tj + c) * 64 + 4 * ti) = v;
            }
            __syncthreads();
#pragma unroll 2
            for (int j = 0; j < 64; j++) {
                float4 s4 = *(const float4*)(Ss + j * 64 + 4 * ti);
                float4 k0 = *(const float4*)(Kr + j * KR_PITCH + 8 * tj);
                float4 k1 = *(const float4*)(Kr + j * KR_PITCH + 8 * tj + 4);
                float sv[4] = {s4.x, s4.y, s4.z, s4.w};
                float kk[8] = {k0.x, k0.y, k0.z, k0.w, k1.x, k1.y, k1.z, k1.w};
#pragma unroll
                for (int r = 0; r < 4; r++)
#pragma unroll
                    for (int c = 0; c < 8; c++) O[r][c] = fmaf(sv[r], kk[c], O[r][c]);
            }
        }
#pragma unroll
        for (int r = 0; r < 4; r++) {
            long long off = ((long long)b * TT + (long long)tb * 64 + 4 * ti + r) * DD + 8 * tj;
            *(float4*)(Out + off)     = make_float4(O[r][0], O[r][1], O[r][2], O[r][3]);
            *(float4*)(Out + off + 4) = make_float4(O[r][4], O[r][5], O[r][6], O[r][7]);
        }
    }
}

// ---------------- final retraction ----------------
__global__ __launch_bounds__(128) void final_kernel(const float* __restrict__ z,
                                                    const float* __restrict__ va,
                                                    float* __restrict__ out) {
    __shared__ float red[4];
    int d = threadIdx.x;
    long long off = (long long)blockIdx.x * DD + d;
    float v = z[off] + va[off];
    float x = v * v;
#pragma unroll
    for (int o = 16; o; o >>= 1) x += __shfl_xor_sync(0xffffffffu, x, o);
    if ((d & 31) == 0) red[d >> 5] = x;
    __syncthreads();
    float ss = red[0] + red[1] + red[2] + red[3];
    out[off] = __fdividef(v, fmaxf(sqrtf(ss), 1e-8f));
}

// ---------------- launch ----------------
extern "C" void kernel_launch(void* const* d_in, const int* in_sizes, int n_in,
                              void* d_out, int out_size) {
    const float* z  = (const float*)d_in[0];
    const float* ck = (const float*)d_in[1];
    const float* cb = (const float*)d_in[2];
    const float* Wq = (const float*)d_in[3];
    const float* bq = (const float*)d_in[4];
    const float* Wk = (const float*)d_in[5];
    const float* bk = (const float*)d_in[6];
    const float* Wo = (const float*)d_in[7];
    const float* bo = (const float*)d_in[8];
    float* out = (float*)d_out;

    float *kh, *mf, *qh, *a0, *a1, *zc, *va;
    cudaGetSymbolAddress((void**)&kh, g_kh);
    cudaGetSymbolAddress((void**)&mf, g_mf);
    cudaGetSymbolAddress((void**)&qh, g_qh);
    cudaGetSymbolAddress((void**)&a0, g_a0);
    cudaGetSymbolAddress((void**)&a1, g_a1);
    cudaGetSymbolAddress((void**)&zc, g_zc);
    cudaGetSymbolAddress((void**)&va, g_va);

    const int GEMM_SMEM = (16384 + 512 + 16) * 4;
    const int ATTN_SMEM = 28928 * 4;
    cudaFuncSetAttribute(gemm_norm_kernel, cudaFuncAttributeMaxDynamicSharedMemorySize, GEMM_SMEM);
    cudaFuncSetAttribute(epilogue_kernel, cudaFuncAttributeMaxDynamicSharedMemorySize, GEMM_SMEM);
    cudaFuncSetAttribute(attn_kernel, cudaFuncAttributeMaxDynamicSharedMemorySize, ATTN_SMEM);

    conv_kernel<<<dim3(TT / 4, BB), dim3(128, 4)>>>(z, ck, cb, mf);
    gemm_norm_kernel<<<BT / 16, 128, GEMM_SMEM>>>(z, Wk, bk, kh);

    const float sws[4] = {1.f / 6.f, 2.f / 6.f, 2.f / 6.f, 1.f / 6.f};
    const float rcs[4] = {0.5f, 0.5f, 1.0f, 0.f};
    const float* zcur = z;
    for (int s = 0; s < 4; s++) {
        gemm_norm_kernel<<<BT / 16, 128, GEMM_SMEM>>>(zcur, Wq, bq, qh);
        attn_kernel<<<dim3(TT / 128, 2, BB), 256, ATTN_SMEM>>>(qh, kh, a0, a1);
        epilogue_kernel<<<BT / 16, 128, GEMM_SMEM>>>(a0, a1, Wo, bo, mf, zcur, z, va, zc,
                                                     sws[s], rcs[s], s == 0 ? 1 : 0, s < 3 ? 1 : 0);
        zcur = zc;
    }
    final_kernel<<<BT, 128>>>(z, va, out);
}

// round 2
// speedup vs baseline: 1.0695x; 1.0695x over previous
#include <cuda_runtime.h>
#include <math.h>

#define BB 2
#define TT 4096
#define DD 128
#define KK 256
#define BT (BB * TT)

// ---------------- scratch ----------------
__device__ float g_kh[BT * DD];
__device__ float g_mf[BT * DD];
__device__ float g_qh[BT * DD];
__device__ float g_a0[BT * DD];
__device__ float g_a1[BT * DD];
__device__ float g_a2[BT * DD];
__device__ float g_a3[BT * DD];
__device__ float g_zc[BT * DD];
__device__ float g_va[BT * DD];

// ---------------- packed f32x2 helpers ----------------
typedef unsigned long long ull;
__device__ __forceinline__ ull dup2(float x) {
    ull r; asm("mov.b64 %0, {%1, %1};" : "=l"(r) : "f"(x)); return r;
}
__device__ __forceinline__ void fma2(ull& d, ull a, ull b) {
    asm("fma.rn.f32x2 %0, %1, %2, %0;" : "+l"(d) : "l"(a), "l"(b));
}
__device__ __forceinline__ float2 unpk(ull v) {
    float2 r; asm("mov.b64 {%0, %1}, %2;" : "=f"(r.x), "=f"(r.y) : "l"(v)); return r;
}

// ---------------- depthwise causal conv ----------------
__global__ __launch_bounds__(512) void conv_kernel(const float* __restrict__ z,
                                                   const float* __restrict__ w,
                                                   const float* __restrict__ bias,
                                                   float* __restrict__ mf) {
    int d = threadIdx.x;
    int t = blockIdx.x * 4 + threadIdx.y;
    int b = blockIdx.y;
    float acc = bias[d];
    int kstart = (KK - 1) - t;
    if (kstart < 0) kstart = 0;
    const float* zp = z + ((long long)b * TT + t - (KK - 1)) * DD + d;
    const float* wp = w + d;
#pragma unroll 4
    for (int k = kstart; k < KK; k++)
        acc = fmaf(zp[(long long)k * DD], wp[(long long)k * DD], acc);
    mf[((long long)b * TT + t) * DD + d] = acc;
}

// ---------------- block reduce of 4 values (128 threads) ----------------
__device__ __forceinline__ void block_reduce4(float v[4], float* red) {
#pragma unroll
    for (int k = 0; k < 4; k++) {
        float x = v[k];
#pragma unroll
        for (int o = 16; o; o >>= 1) x += __shfl_xor_sync(0xffffffffu, x, o);
        if ((threadIdx.x & 31) == 0) red[((threadIdx.x >> 5) << 2) + k] = x;
    }
    __syncthreads();
#pragma unroll
    for (int k = 0; k < 4; k++) v[k] = red[k] + red[4 + k] + red[8 + k] + red[12 + k];
    __syncthreads();
}

// ---------------- Y = sphere_norm(X @ W + bias) ----------------
__global__ __launch_bounds__(128) void gemm_norm_kernel(const float* __restrict__ X,
                                                        const float* __restrict__ W,
                                                        const float* __restrict__ bias,
                                                        float* __restrict__ Y) {
    extern __shared__ float sm[];
    float* Ws  = sm;           // 128*128
    float* xs  = sm + 16384;   // 4*128
    float* red = sm + 16896;   // 16
    int d = threadIdx.x;
    for (int idx = d; idx < 16384; idx += 128) Ws[idx] = W[idx];
    float bv = bias[d];
    __syncthreads();
    long long row0 = (long long)blockIdx.x * 16;
    for (int g = 0; g < 16; g += 4) {
#pragma unroll
        for (int k = 0; k < 4; k++) xs[k * 128 + d] = X[(row0 + g + k) * DD + d];
        __syncthreads();
        float a0 = bv, a1 = bv, a2 = bv, a3 = bv;
#pragma unroll 4
        for (int j = 0; j < 128; j++) {
            float wv = Ws[j * 128 + d];
            a0 = fmaf(xs[j], wv, a0);
            a1 = fmaf(xs[128 + j], wv, a1);
            a2 = fmaf(xs[256 + j], wv, a2);
            a3 = fmaf(xs[384 + j], wv, a3);
        }
        float acc[4] = {a0, a1, a2, a3};
        float v[4] = {a0 * a0, a1 * a1, a2 * a2, a3 * a3};
        block_reduce4(v, red);
#pragma unroll
        for (int k = 0; k < 4; k++) {
            float norm = fmaxf(sqrtf(v[k]), 1e-8f);
            Y[(row0 + g + k) * DD + d] = __fdividef(acc[k], norm);
        }
        __syncthreads();
    }
}

// ---------------- fused epilogue + next-stage q projection ----------------
__global__ __launch_bounds__(128) void epilogue_kernel(
    const float* __restrict__ A0, const float* __restrict__ A1,
    const float* __restrict__ A2, const float* __restrict__ A3,
    const float* __restrict__ Wo, const float* __restrict__ bo,
    const float* __restrict__ Wq, const float* __restrict__ bq,
    const float* __restrict__ mf, const float* __restrict__ zin,
    const float* __restrict__ zbase, float* __restrict__ vacc,
    float* __restrict__ zc, float* __restrict__ qh,
    float sw, float rc, int first, int has_next) {
    extern __shared__ float sm[];
    float* Wos = sm;            // 16384
    float* Wqs = sm + 16384;    // 16384
    float* xs  = sm + 32768;    // 512
    float* red = sm + 33280;    // 16
    int d = threadIdx.x;
    for (int idx = d; idx < 16384; idx += 128) { Wos[idx] = Wo[idx]; Wqs[idx] = Wq[idx]; }
    float bov = bo[d], bqv = bq[d];
    __syncthreads();
    long long row0 = (long long)blockIdx.x * 16;
    for (int g = 0; g < 16; g += 4) {
#pragma unroll
        for (int k = 0; k < 4; k++) {
            long long off = (row0 + g + k) * DD + d;
            xs[k * 128 + d] = A0[off] + A1[off] + A2[off] + A3[off];
        }
        __syncthreads();
        float a0 = bov, a1 = bov, a2 = bov, a3 = bov;
#pragma unroll 4
        for (int j = 0; j < 128; j++) {
            float wv = Wos[j * 128 + d];
            a0 = fmaf(xs[j], wv, a0);
            a1 = fmaf(xs[128 + j], wv, a1);
            a2 = fmaf(xs[256 + j], wv, a2);
            a3 = fmaf(xs[384 + j], wv, a3);
        }
        float acc[4] = {a0, a1, a2, a3};
        float tot[4], zcd[4], v[4];
#pragma unroll
        for (int k = 0; k < 4; k++) {
            long long off = (row0 + g + k) * DD + d;
            tot[k] = acc[k] + mf[off];
            zcd[k] = zin[off];
            v[k]   = tot[k] * zcd[k];
        }
        block_reduce4(v, red);
        float proj[4];
#pragma unroll
        for (int k = 0; k < 4; k++) {
            proj[k] = tot[k] - v[k] * zcd[k];
            long long off = (row0 + g + k) * DD + d;
            float vp = first ? 0.f : vacc[off];
            vacc[off] = vp + sw * proj[k];
        }
        if (has_next) {
            float zn[4], u[4];
#pragma unroll
            for (int k = 0; k < 4; k++) {
                long long off = (row0 + g + k) * DD + d;
                zn[k] = zbase[off] + rc * proj[k];
                u[k]  = zn[k] * zn[k];
            }
            block_reduce4(u, red);
#pragma unroll
            for (int k = 0; k < 4; k++) {
                long long off = (row0 + g + k) * DD + d;
                float znv = __fdividef(zn[k], fmaxf(sqrtf(u[k]), 1e-8f));
                zc[off] = znv;
                xs[k * 128 + d] = znv;
            }
            __syncthreads();
            float q0 = bqv, q1 = bqv, q2 = bqv, q3 = bqv;
#pragma unroll 4
            for (int j = 0; j < 128; j++) {
                float wv = Wqs[j * 128 + d];
                q0 = fmaf(xs[j], wv, q0);
                q1 = fmaf(xs[128 + j], wv, q1);
                q2 = fmaf(xs[256 + j], wv, q2);
                q3 = fmaf(xs[384 + j], wv, q3);
            }
            float qa[4] = {q0, q1, q2, q3};
            float w2[4] = {q0 * q0, q1 * q1, q2 * q2, q3 * q3};
            block_reduce4(w2, red);
#pragma unroll
            for (int k = 0; k < 4; k++) {
                long long off = (row0 + g + k) * DD + d;
                qh[off] = __fdividef(qa[k], fmaxf(sqrtf(w2[k]), 1e-8f));
            }
        }
        __syncthreads();
    }
}

// ---------------- causal sin-attention (FFMA2, quarter-split) ----------------
#define KR_PITCH 132
#define SS_PITCH 68
// smem floats: Qt 8192 | Ktc 4096 | Kr 8448 | Ss 4352  -> 25088 floats (100352 B)

__global__ __launch_bounds__(256, 2) void attn_kernel(const float* __restrict__ Q,
                                                      const float* __restrict__ Kh,
                                                      float* __restrict__ O0,
                                                      float* __restrict__ O1,
                                                      float* __restrict__ O2,
                                                      float* __restrict__ O3) {
    extern __shared__ float sm[];
    float* Qt  = sm;            // [d(128)][i(64)]
    float* Ktc = sm + 8192;     // [d(64 chunk)][j(64)]
    float* Kr  = sm + 12288;    // [j(64)][d(128) pitch 132]
    float* Ss  = sm + 20736;    // [j(64)][i(64) pitch 68]
    const int tid = threadIdx.x;
    const int b = blockIdx.z, qq = blockIdx.y, p = blockIdx.x;
    float* Out = (qq == 0) ? O0 : (qq == 1) ? O1 : (qq == 2) ? O2 : O3;
    const int tj = tid & 15, ti = tid >> 4;
    const float* Qb = Q + (long long)b * TT * DD;
    const float* Kb = Kh + (long long)b * TT * DD;

    for (int rep = 0; rep < 2; rep++) {
        int tb = rep ? (TT / 64 - 1 - p) : p;
        __syncthreads();
        // Q tile -> Qt [d][i]
        for (int idx = tid; idx < 2048; idx += 256) {
            int i = idx & 63, d0 = (idx >> 6) << 2;
            float4 v = *(const float4*)(Qb + ((long long)tb * 64 + i) * DD + d0);
            Qt[(d0 + 0) * 64 + i] = v.x;
            Qt[(d0 + 1) * 64 + i] = v.y;
            Qt[(d0 + 2) * 64 + i] = v.z;
            Qt[(d0 + 3) * 64 + i] = v.w;
        }
        ull O2a[4][4];
#pragma unroll
        for (int r = 0; r < 4; r++)
#pragma unroll
            for (int c = 0; c < 4; c++) O2a[r][c] = 0ull;

        int nsb = tb + 1;
        int sb0 = (nsb * qq) >> 2;
        int sb1 = (nsb * (qq + 1)) >> 2;
        for (int sb = sb0; sb < sb1; sb++) {
            ull S2[4][2];
#pragma unroll
            for (int r = 0; r < 4; r++) { S2[r][0] = 0ull; S2[r][1] = 0ull; }
            // two 64-d chunks
#pragma unroll 1
            for (int c = 0; c < 2; c++) {
                __syncthreads();
                for (int idx = tid; idx < 1024; idx += 256) {
                    int j = idx & 63, d0 = (idx >> 6) << 2;
                    float4 v = *(const float4*)(Kb + ((long long)sb * 64 + j) * DD + c * 64 + d0);
                    Ktc[(d0 + 0) * 64 + j] = v.x;
                    Ktc[(d0 + 1) * 64 + j] = v.y;
                    Ktc[(d0 + 2) * 64 + j] = v.z;
                    Ktc[(d0 + 3) * 64 + j] = v.w;
                    *(float4*)(Kr + j * KR_PITCH + c * 64 + d0) = v;
                }
                __syncthreads();
#pragma unroll 4
                for (int dd = 0; dd < 64; dd++) {
                    float4 q4 = *(const float4*)(Qt + (c * 64 + dd) * 64 + 4 * ti);
                    ulonglong2 kk = *(const ulonglong2*)(Ktc + dd * 64 + 4 * tj);
                    ull q0 = dup2(q4.x), q1 = dup2(q4.y), q2 = dup2(q4.z), q3 = dup2(q4.w);
                    fma2(S2[0][0], q0, kk.x); fma2(S2[0][1], q0, kk.y);
                    fma2(S2[1][0], q1, kk.x); fma2(S2[1][1], q1, kk.y);
                    fma2(S2[2][0], q2, kk.x); fma2(S2[2][1], q2, kk.y);
                    fma2(S2[3][0], q3, kk.x); fma2(S2[3][1], q3, kk.y);
                }
            }
            // sin (deg-9 odd poly, |x|<=1) + causal mask on diag tile
            const bool diag = (sb == tb);
            float S[4][4];
#pragma unroll
            for (int r = 0; r < 4; r++) {
                float2 a = unpk(S2[r][0]);
                float2 bb = unpk(S2[r][1]);
                S[r][0] = a.x; S[r][1] = a.y; S[r][2] = bb.x; S[r][3] = bb.y;
            }
#pragma unroll
            for (int r = 0; r < 4; r++)
#pragma unroll
                for (int c = 0; c < 4; c++) {
                    float x  = S[r][c];
                    float x2 = x * x;
                    float pp = fmaf(x2, 2.7557319e-06f, -1.9841270e-04f);
                    pp = fmaf(x2, pp, 8.3333333e-03f);
                    pp = fmaf(x2, pp, -1.6666667e-01f);
                    float sv = fmaf(x * x2, pp, x);
                    if (diag && (4 * tj + c) > (4 * ti + r)) sv = 0.f;
                    S[r][c] = sv;
                }
#pragma unroll
            for (int c = 0; c < 4; c++)
                *(float4*)(Ss + (4 * tj + c) * SS_PITCH + 4 * ti) =
                    make_float4(S[0][c], S[1][c], S[2][c], S[3][c]);
            __syncthreads();
            // O accumulation: O[i][d] += S[i][j] * K[j][d]
#pragma unroll 2
            for (int j = 0; j < 64; j++) {
                float4 s4 = *(const float4*)(Ss + j * SS_PITCH + 4 * ti);
                ulonglong2 ka = *(const ulonglong2*)(Kr + j * KR_PITCH + 8 * tj);
                ulonglong2 kb2 = *(const ulonglong2*)(Kr + j * KR_PITCH + 8 * tj + 4);
                ull s0 = dup2(s4.x), s1 = dup2(s4.y), s2 = dup2(s4.z), s3 = dup2(s4.w);
                fma2(O2a[0][0], s0, ka.x); fma2(O2a[0][1], s0, ka.y);
                fma2(O2a[0][2], s0, kb2.x); fma2(O2a[0][3], s0, kb2.y);
                fma2(O2a[1][0], s1, ka.x); fma2(O2a[1][1], s1, ka.y);
                fma2(O2a[1][2], s1, kb2.x); fma2(O2a[1][3], s1, kb2.y);
                fma2(O2a[2][0], s2, ka.x); fma2(O2a[2][1], s2, ka.y);
                fma2(O2a[2][2], s2, kb2.x); fma2(O2a[2][3], s2, kb2.y);
                fma2(O2a[3][0], s3, ka.x); fma2(O2a[3][1], s3, ka.y);
                fma2(O2a[3][2], s3, kb2.x); fma2(O2a[3][3], s3, kb2.y);
            }
        }
#pragma unroll
        for (int r = 0; r < 4; r++) {
            float2 p0 = unpk(O2a[r][0]), p1 = unpk(O2a[r][1]);
            float2 p2 = unpk(O2a[r][2]), p3 = unpk(O2a[r][3]);
            long long off = ((long long)b * TT + (long long)tb * 64 + 4 * ti + r) * DD + 8 * tj;
            *(float4*)(Out + off)     = make_float4(p0.x, p0.y, p1.x, p1.y);
            *(float4*)(Out + off + 4) = make_float4(p2.x, p2.y, p3.x, p3.y);
        }
    }
}

// ---------------- final retraction ----------------
__global__ __launch_bounds__(128) void final_kernel(const float* __restrict__ z,
                                                    const float* __restrict__ va,
                                                    float* __restrict__ out) {
    __shared__ float red[4];
    int d = threadIdx.x;
    long long off = (long long)blockIdx.x * DD + d;
    float v = z[off] + va[off];
    float x = v * v;
#pragma unroll
    for (int o = 16; o; o >>= 1) x += __shfl_xor_sync(0xffffffffu, x, o);
    if ((d & 31) == 0) red[d >> 5] = x;
    __syncthreads();
    float ss = red[0] + red[1] + red[2] + red[3];
    out[off] = __fdividef(v, fmaxf(sqrtf(ss), 1e-8f));
}

// ---------------- launch ----------------
extern "C" void kernel_launch(void* const* d_in, const int* in_sizes, int n_in,
                              void* d_out, int out_size) {
    const float* z  = (const float*)d_in[0];
    const float* ck = (const float*)d_in[1];
    const float* cb = (const float*)d_in[2];
    const float* Wq = (const float*)d_in[3];
    const float* bq = (const float*)d_in[4];
    const float* Wk = (const float*)d_in[5];
    const float* bk = (const float*)d_in[6];
    const float* Wo = (const float*)d_in[7];
    const float* bo = (const float*)d_in[8];
    float* out = (float*)d_out;

    float *kh, *mf, *qh, *a0, *a1, *a2, *a3, *zc, *va;
    cudaGetSymbolAddress((void**)&kh, g_kh);
    cudaGetSymbolAddress((void**)&mf, g_mf);
    cudaGetSymbolAddress((void**)&qh, g_qh);
    cudaGetSymbolAddress((void**)&a0, g_a0);
    cudaGetSymbolAddress((void**)&a1, g_a1);
    cudaGetSymbolAddress((void**)&a2, g_a2);
    cudaGetSymbolAddress((void**)&a3, g_a3);
    cudaGetSymbolAddress((void**)&zc, g_zc);
    cudaGetSymbolAddress((void**)&va, g_va);

    const int GEMM_SMEM = (16384 + 512 + 16) * 4;
    const int EPI_SMEM  = (32768 + 512 + 16) * 4;
    const int ATTN_SMEM = 25088 * 4;
    cudaFuncSetAttribute(gemm_norm_kernel, cudaFuncAttributeMaxDynamicSharedMemorySize, GEMM_SMEM);
    cudaFuncSetAttribute(epilogue_kernel, cudaFuncAttributeMaxDynamicSharedMemorySize, EPI_SMEM);
    cudaFuncSetAttribute(attn_kernel, cudaFuncAttributeMaxDynamicSharedMemorySize, ATTN_SMEM);

    conv_kernel<<<dim3(TT / 4, BB), dim3(128, 4)>>>(z, ck, cb, mf);
    gemm_norm_kernel<<<BT / 16, 128, GEMM_SMEM>>>(z, Wk, bk, kh);
    gemm_norm_kernel<<<BT / 16, 128, GEMM_SMEM>>>(z, Wq, bq, qh);

    const float sws[4] = {1.f / 6.f, 2.f / 6.f, 2.f / 6.f, 1.f / 6.f};
    const float rcs[4] = {0.5f, 0.5f, 1.0f, 0.f};
    const float* zcur = z;
    for (int s = 0; s < 4; s++) {
        attn_kernel<<<dim3(32, 4, BB), 256, ATTN_SMEM>>>(qh, kh, a0, a1, a2, a3);
        epilogue_kernel<<<BT / 16, 128, EPI_SMEM>>>(a0, a1, a2, a3, Wo, bo, Wq, bq,
                                                    mf, zcur, z, va, zc, qh,
                                                    sws[s], rcs[s], s == 0 ? 1 : 0, s < 3 ? 1 : 0);
        zcur = zc;
    }
    final_kernel<<<BT, 128>>>(z, va, out);
}